// round 6
// baseline (speedup 1.0000x reference)
#include <cuda_runtime.h>
#include <cuda_bf16.h>
#include <math.h>

// Problem constants
#define BB 4
#define SS 1024
#define KK 32
#define VV 32000
#define ROWS (BB * SS)        // 4096
#define FULL 0xFFFFFFFFu

#define PRE_THREADS 256
#define ROWS_PER_BLOCK (PRE_THREADS / 32)   // 8 rows (one per warp)

// Scratch for per-row probs (no device allocation allowed -> __device__ global)
__device__ float g_probs[ROWS * KK];        // 512 KB

// ---------------------------------------------------------------------------
// Kernel 1: per-row math -> probs into scratch. Does NOT touch `out`.
// ---------------------------------------------------------------------------
__global__ __launch_bounds__(PRE_THREADS)
void robust_compute_kernel(
    const int*   __restrict__ tgt_index,            // [ROWS, 32]
    const float* __restrict__ knn_dists,            // [ROWS, 32]
    const float* __restrict__ knn_key_feature,      // [ROWS, 32]
    const float* __restrict__ network_select_probs, // [ROWS, 32]
    const float* __restrict__ fc1_w1,               // [2,4]
    const float* __restrict__ fc1_b1,               // [4]
    const float* __restrict__ fc1_w2,               // [4,1]
    const float* __restrict__ fc1_b2,               // [1]
    const float* __restrict__ fc2_w1,               // [64,32]
    const float* __restrict__ fc2_b1,               // [32]
    const float* __restrict__ fc2_w2,               // [32,2]
    const float* __restrict__ fc2_b2)               // [2]
{
    const int tid  = threadIdx.x;
    const int lane = tid & 31;
    const int row  = blockIdx.x * ROWS_PER_BLOCK + (tid >> 5);

    const int base = row * KK + lane;
    const int   t  = tgt_index[base];
    const float d  = knn_dists[base];
    const float lkf = logf(knn_key_feature[base]);
    const float lsp = logf(network_select_probs[base]);

    // ---- label_counts via match/ballot (replaces O(K^2) shuffle scan) ----
    // first-occurrence flag: this lane is the lowest lane holding value t
    unsigned mmask  = __match_any_sync(FULL, t);
    int      leader = __ffs(mmask) - 1;
    int      fo     = (t != 0 && leader == lane) ? 1 : 0;
    unsigned bal    = __ballot_sync(FULL, fo);
    unsigned lml;
    asm("mov.u32 %0, %%lanemask_le;" : "=r"(lml));
    const float lc = (float)__popc(bal & lml);   // distinct nonzero labels in prefix [0..lane]

    // ---- noise_logit: Linear(2,4) -> tanh -> Linear(4,1) ----
    float noise = fc1_b2[0];
    #pragma unroll
    for (int j = 0; j < 4; j++) {
        float h = tanhf(lkf * fc1_w1[j] + lsp * fc1_w1[4 + j] + fc1_b1[j]);
        noise += h * fc1_w2[j];
    }

    // ---- fc2: Linear(64,32)->tanh->Linear(32,2)[1]; lane = hidden unit ----
    float acc = fc2_b1[lane];
    #pragma unroll
    for (int m = 0; m < KK; m++) {
        float dm = __shfl_sync(FULL, d, m);
        acc = fmaf(dm, fc2_w1[m * 32 + lane], acc);
    }
    #pragma unroll
    for (int m = 0; m < KK; m++) {
        float lcm = __shfl_sync(FULL, lc, m);
        acc = fmaf(lcm, fc2_w1[(KK + m) * 32 + lane], acc);
    }
    float h = tanhf(acc);

    // lambda_logit[1] warp-reduce
    float part = h * fc2_w2[lane * 2 + 1];
    #pragma unroll
    for (int off = 16; off >= 1; off >>= 1)
        part += __shfl_xor_sync(FULL, part, off);
    const float tempe = 1.0f / (1.0f + expf(-(part + fc2_b2[1])));

    // ---- probs = softmax(-d * tempe + noise) over K ----
    float logit = fmaf(-d, tempe, noise);
    float mx = logit;
    #pragma unroll
    for (int off = 16; off >= 1; off >>= 1)
        mx = fmaxf(mx, __shfl_xor_sync(FULL, mx, off));
    float e = expf(logit - mx);
    float s = e;
    #pragma unroll
    for (int off = 16; off >= 1; off >>= 1)
        s += __shfl_xor_sync(FULL, s, off);

    g_probs[base] = e / s;
}

// ---------------------------------------------------------------------------
// Kernel 2: commit — one thread per (row,k): atomicAdd into zeroed output.
// Dependent chain: 2 coalesced loads + 1 RED.
// ---------------------------------------------------------------------------
#define POST_THREADS 256

__global__ __launch_bounds__(POST_THREADS)
void robust_commit_kernel(
    const int* __restrict__ tgt_index,   // [ROWS*32]
    float*     __restrict__ out)         // [ROWS, 32000]
{
    const int i = blockIdx.x * POST_THREADS + threadIdx.x;  // 0 .. ROWS*KK-1
    const int row = i >> 5;                                  // i / 32
    const int t   = tgt_index[i];
    const float p = g_probs[i];
    atomicAdd(out + (size_t)row * VV + t, p);
}

extern "C" void kernel_launch(void* const* d_in, const int* in_sizes, int n_in,
                              void* d_out, int out_size)
{
    // metadata order (setup_inputs order):
    // 0 tgt_index i32, 1 knn_dists f32, 2 knn_key_feature f32,
    // 3 network_probs f32 (UNUSED — dead code in reference),
    // 4 network_select_probs f32, 5 dfc_w (UNUSED), 6 dfc_b (UNUSED),
    // 7 fc1_w1, 8 fc1_b1, 9 fc1_w2, 10 fc1_b2,
    // 11 fc2_w1, 12 fc2_b1, 13 fc2_w2, 14 fc2_b2
    const int*   tgt  = (const int*)  d_in[0];
    const float* kd   = (const float*)d_in[1];
    const float* kkf  = (const float*)d_in[2];
    const float* nsp  = (const float*)d_in[4];
    const float* f1w1 = (const float*)d_in[7];
    const float* f1b1 = (const float*)d_in[8];
    const float* f1w2 = (const float*)d_in[9];
    const float* f1b2 = (const float*)d_in[10];
    const float* f2w1 = (const float*)d_in[11];
    const float* f2b1 = (const float*)d_in[12];
    const float* f2w2 = (const float*)d_in[13];
    const float* f2b2 = (const float*)d_in[14];
    float* out = (float*)d_out;

    // 1) Per-row math into scratch (independent of `out`).
    robust_compute_kernel<<<ROWS / ROWS_PER_BLOCK, PRE_THREADS>>>(
        tgt, kd, kkf, nsp,
        f1w1, f1b1, f1w2, f1b2,
        f2w1, f2b1, f2w2, f2b2);

    // 2) Bulk zero via the driver's tuned fill path (~7.3 TB/s).
    cudaMemsetAsync(out, 0, (size_t)ROWS * VV * sizeof(float), 0);

    // 3) Minimal-latency commit: coalesced loads + scattered RED.ADD.
    robust_commit_kernel<<<(ROWS * KK) / POST_THREADS, POST_THREADS>>>(tgt, out);
}